// round 7
// baseline (speedup 1.0000x reference)
#include <cuda_runtime.h>

// ---------------------------------------------------------------------------
// CumulantSOAP: single-pass raw moments S1..S5 per column of X (N x P),
// 2-stage fp32 partial reduction; final kernel fuses slice-fold + fp64
// cumulant algebra + mu subtraction + projection (cum - mu) @ W.
// ---------------------------------------------------------------------------

#define NM    5
#define GMAX  592
#define PMAX  1024
#define NSLC  8          // stage-A slice count

// Scratch (no cudaMalloc allowed)
__device__ float g_partial[NM * GMAX * PMAX];    // [m][block][col]
__device__ float g_partial2[NM * NSLC * PMAX];   // [m][slice][col]
__device__ float g_cum[NM * PMAX];               // generic-fallback only

// ---- packed f32x2 helpers (Blackwell FFMA2 path, PTX-only) ----------------
static __device__ __forceinline__ unsigned long long f2_mul(unsigned long long a,
                                                            unsigned long long b) {
    unsigned long long d;
    asm("mul.rn.f32x2 %0, %1, %2;" : "=l"(d) : "l"(a), "l"(b));
    return d;
}
static __device__ __forceinline__ unsigned long long f2_add(unsigned long long a,
                                                            unsigned long long b) {
    unsigned long long d;
    asm("add.rn.f32x2 %0, %1, %2;" : "=l"(d) : "l"(a), "l"(b));
    return d;
}
static __device__ __forceinline__ unsigned long long f2_fma(unsigned long long a,
                                                            unsigned long long b,
                                                            unsigned long long c) {
    unsigned long long d;
    asm("fma.rn.f32x2 %0, %1, %2, %3;" : "=l"(d) : "l"(a), "l"(b), "l"(c));
    return d;
}
static __device__ __forceinline__ float2 f2_unpack(unsigned long long v) {
    float2 f;
    asm("mov.b64 {%0, %1}, %2;" : "=f"(f.x), "=f"(f.y) : "l"(v));
    return f;
}

// Accumulate one packed pair (2 elements) into 5 packed moment accumulators.
#define ACC(u, s1, s2, s3, s4, s5)                         \
    do {                                                   \
        unsigned long long _x2 = f2_mul((u), (u));         \
        unsigned long long _x3 = f2_mul(_x2, (u));         \
        (s1) = f2_add((s1), (u));                          \
        (s2) = f2_fma((u), (u), (s2));                     \
        (s3) = f2_fma(_x2, (u), (s3));                     \
        (s4) = f2_fma(_x2, _x2, (s4));                     \
        (s5) = f2_fma(_x3, _x2, (s5));                     \
    } while (0)

// ---------------------------------------------------------------------------
// Kernel 1: streaming raw moments. Block b handles rows b, b+G, b+2G, ...
// Thread t handles 4 consecutive columns (one LDG.128 per row), streaming
// (evict-first) loads since X is touched exactly once.
// ---------------------------------------------------------------------------
__global__ __launch_bounds__(256, 4)
void k_moments(const float* __restrict__ X, int N, int P, int G) {
    const int b = blockIdx.x;
    const int tid = threadIdx.x;
    const int col4 = tid * 4;

    unsigned long long s1a = 0ULL, s2a = 0ULL, s3a = 0ULL, s4a = 0ULL, s5a = 0ULL;
    unsigned long long s1b = 0ULL, s2b = 0ULL, s3b = 0ULL, s4b = 0ULL, s5b = 0ULL;

    const char* base = (const char*)(X + col4);
    const size_t rowBytes = (size_t)P * sizeof(float);

    int r = b;
    const int G4 = 4 * G;
    for (; r + 3 * G < N; r += G4) {
        ulonglong2 v0 = __ldcs((const ulonglong2*)(base + (size_t)r * rowBytes));
        ulonglong2 v1 = __ldcs((const ulonglong2*)(base + (size_t)(r + G) * rowBytes));
        ulonglong2 v2 = __ldcs((const ulonglong2*)(base + (size_t)(r + 2 * G) * rowBytes));
        ulonglong2 v3 = __ldcs((const ulonglong2*)(base + (size_t)(r + 3 * G) * rowBytes));
        ACC(v0.x, s1a, s2a, s3a, s4a, s5a);
        ACC(v0.y, s1b, s2b, s3b, s4b, s5b);
        ACC(v1.x, s1a, s2a, s3a, s4a, s5a);
        ACC(v1.y, s1b, s2b, s3b, s4b, s5b);
        ACC(v2.x, s1a, s2a, s3a, s4a, s5a);
        ACC(v2.y, s1b, s2b, s3b, s4b, s5b);
        ACC(v3.x, s1a, s2a, s3a, s4a, s5a);
        ACC(v3.y, s1b, s2b, s3b, s4b, s5b);
    }
    for (; r < N; r += G) {
        ulonglong2 v = __ldcs((const ulonglong2*)(base + (size_t)r * rowBytes));
        ACC(v.x, s1a, s2a, s3a, s4a, s5a);
        ACC(v.y, s1b, s2b, s3b, s4b, s5b);
    }

    const size_t GP = (size_t)G * P;
    float* out = g_partial + (size_t)b * P + col4;
    float2 a, bb;
    a = f2_unpack(s1a); bb = f2_unpack(s1b);
    *(float4*)(out + 0 * GP) = make_float4(a.x, a.y, bb.x, bb.y);
    a = f2_unpack(s2a); bb = f2_unpack(s2b);
    *(float4*)(out + 1 * GP) = make_float4(a.x, a.y, bb.x, bb.y);
    a = f2_unpack(s3a); bb = f2_unpack(s3b);
    *(float4*)(out + 2 * GP) = make_float4(a.x, a.y, bb.x, bb.y);
    a = f2_unpack(s4a); bb = f2_unpack(s4b);
    *(float4*)(out + 3 * GP) = make_float4(a.x, a.y, bb.x, bb.y);
    a = f2_unpack(s5a); bb = f2_unpack(s5b);
    *(float4*)(out + 4 * GP) = make_float4(a.x, a.y, bb.x, bb.y);
}

// ---------------------------------------------------------------------------
// Kernel 2a: stage-A reduction. grid = (P/32, NSLC). Block = 256 threads
// (32 cols x 8 subslices). All loads L2-hit (partials just written).
// ---------------------------------------------------------------------------
__global__ __launch_bounds__(256)
void k_reduceA(int P, int G) {
    const int cl = threadIdx.x & 31;
    const int ss = threadIdx.x >> 5;                 // 0..7
    const int col = blockIdx.x * 32 + cl;
    const int gs = blockIdx.y;                       // 0..NSLC-1
    const int chunk = G / NSLC;
    const int b0 = gs * chunk;
    const int b1 = (gs == NSLC - 1) ? G : b0 + chunk;
    const size_t GP = (size_t)G * P;

    float acc[NM] = {0.f, 0.f, 0.f, 0.f, 0.f};
    for (int b = b0 + ss; b < b1; b += 8) {
        const size_t off = (size_t)b * P + col;
#pragma unroll
        for (int m = 0; m < NM; m++)
            acc[m] += g_partial[(size_t)m * GP + off];
    }

    __shared__ float smem[NM][8][32];
#pragma unroll
    for (int m = 0; m < NM; m++) smem[m][ss][cl] = acc[m];
    __syncthreads();

    if (ss == 0) {
#pragma unroll
        for (int m = 0; m < NM; m++) {
            float v = 0.f;
#pragma unroll
            for (int j = 0; j < 8; j++) v += smem[m][j][cl];
            g_partial2[(size_t)m * (NSLC * PMAX) + (size_t)gs * PMAX + col] = v;
        }
    }
}

// ---------------------------------------------------------------------------
// Kernel 3 (fused finish, K == 8): one 1024-thread block; thread = column.
// W prefetched with 10 independent float4 loads per thread (max MLP),
// overlapped with the L2-hot slice fold + fp64 cumulant algebra; then a
// block reduction of 8 projection partials.
// ---------------------------------------------------------------------------
__global__ __launch_bounds__(1024)
void k_finish8(const float* __restrict__ mu, const float* __restrict__ W,
               float* __restrict__ out, int N, int P) {
    const int tid = threadIdx.x;
    const int col = tid;
    const bool active = (col < P);

    // --- prefetch W rows for this column: 40 contiguous floats (16B-aligned) ---
    float4 w[10];
    if (active) {
        const float4* wp = (const float4*)(W + (size_t)col * NM * 8);
#pragma unroll
        for (int i = 0; i < 10; i++) w[i] = __ldg(&wp[i]);
    }

    float a0 = 0.f, a1 = 0.f, a2 = 0.f, a3 = 0.f;
    float a4 = 0.f, a5 = 0.f, a6 = 0.f, a7 = 0.f;

    if (active) {
        // --- prefetch mu as scalars (col*5 stride is NOT 16B-aligned) ---
        const float* mup = mu + (size_t)col * NM;
        float muv[NM];
#pragma unroll
        for (int q = 0; q < NM; q++) muv[q] = __ldg(&mup[q]);

        // --- fold the 8 slice partials (L2-hot) ---
        double t[NM];
#pragma unroll
        for (int m = 0; m < NM; m++) {
            float v = 0.f;
#pragma unroll
            for (int j = 0; j < NSLC; j++)
                v += g_partial2[(size_t)m * (NSLC * PMAX) + (size_t)j * PMAX + col];
            t[m] = (double)v;
        }

        // --- cumulants (fp64 algebra, tiny) ---
        const double invN = 1.0 / (double)N;
        const double m1 = t[0] * invN;
        const double r2 = t[1] * invN;
        const double r3 = t[2] * invN;
        const double r4 = t[3] * invN;
        const double r5 = t[4] * invN;
        const double m2 = m1 * m1;
        const double m3 = m2 * m1;

        const double mu2 = r2 - m2;
        const double mu3 = r3 - 3.0 * m1 * r2 + 2.0 * m3;
        const double mu5 = r5 - 5.0 * m1 * r4 + 10.0 * m2 * r3 - 10.0 * m3 * r2
                           + 4.0 * m3 * m2;

        float c[NM];
        c[0] = (float)m1          - muv[0];
        c[1] = 0.f                - muv[1];          // mean(centered) == 0
        c[2] = (float)mu2         - muv[2];
        c[3] = (float)(mu3 - 3.0 * mu2 * mu2)  - muv[3];
        c[4] = (float)(mu5 - 10.0 * mu2 * mu3) - muv[4];

        // --- projection partials for this column ---
#pragma unroll
        for (int q = 0; q < NM; q++) {
            const float cc = c[q];
            const float4 w0 = w[q * 2];
            const float4 w1 = w[q * 2 + 1];
            a0 += cc * w0.x; a1 += cc * w0.y; a2 += cc * w0.z; a3 += cc * w0.w;
            a4 += cc * w1.x; a5 += cc * w1.y; a6 += cc * w1.z; a7 += cc * w1.w;
        }
    }

    // --- block reduction of 8 accumulators ---
#pragma unroll
    for (int o = 16; o > 0; o >>= 1) {
        a0 += __shfl_down_sync(0xffffffffu, a0, o);
        a1 += __shfl_down_sync(0xffffffffu, a1, o);
        a2 += __shfl_down_sync(0xffffffffu, a2, o);
        a3 += __shfl_down_sync(0xffffffffu, a3, o);
        a4 += __shfl_down_sync(0xffffffffu, a4, o);
        a5 += __shfl_down_sync(0xffffffffu, a5, o);
        a6 += __shfl_down_sync(0xffffffffu, a6, o);
        a7 += __shfl_down_sync(0xffffffffu, a7, o);
    }

    __shared__ float sred[32][8];
    const int wrp = tid >> 5;
    if ((tid & 31) == 0) {
        sred[wrp][0] = a0; sred[wrp][1] = a1; sred[wrp][2] = a2; sred[wrp][3] = a3;
        sred[wrp][4] = a4; sred[wrp][5] = a5; sred[wrp][6] = a6; sred[wrp][7] = a7;
    }
    __syncthreads();
    if (tid < 8) {
        float v = 0.f;
#pragma unroll
        for (int j = 0; j < 32; j++) v += sred[j][tid];
        out[tid] = v;
    }
}

// ---------------------------------------------------------------------------
// Generic fallback path (K != 8 or P > 1024)
// ---------------------------------------------------------------------------
__global__ __launch_bounds__(128)
void k_reduceB(const float* __restrict__ mu, int N, int P) {
    const int col = blockIdx.x * 128 + threadIdx.x;
    if (col >= P) return;

    double t[NM];
#pragma unroll
    for (int m = 0; m < NM; m++) {
        float v = 0.f;
#pragma unroll
        for (int j = 0; j < NSLC; j++)
            v += g_partial2[(size_t)m * (NSLC * PMAX) + (size_t)j * PMAX + col];
        t[m] = (double)v;
    }

    const double invN = 1.0 / (double)N;
    const double m1 = t[0] * invN;
    const double r2 = t[1] * invN;
    const double r3 = t[2] * invN;
    const double r4 = t[3] * invN;
    const double r5 = t[4] * invN;
    const double m2 = m1 * m1;
    const double m3 = m2 * m1;

    const double mu2 = r2 - m2;
    const double mu3 = r3 - 3.0 * m1 * r2 + 2.0 * m3;
    const double mu5 = r5 - 5.0 * m1 * r4 + 10.0 * m2 * r3 - 10.0 * m3 * r2
                       + 4.0 * m3 * m2;

    const int j = col * NM;
    g_cum[j + 0] = (float)m1 - mu[j + 0];
    g_cum[j + 1] = 0.f - mu[j + 1];
    g_cum[j + 2] = (float)mu2 - mu[j + 2];
    g_cum[j + 3] = (float)(mu3 - 3.0 * mu2 * mu2) - mu[j + 3];
    g_cum[j + 4] = (float)(mu5 - 10.0 * mu2 * mu3) - mu[j + 4];
}

__global__ void k_project_gen(const float* __restrict__ W, float* __restrict__ out,
                              int P5, int K) {
    const int w = blockIdx.x;
    const int lane = threadIdx.x;
    float acc = 0.f;
    for (int i = lane; i < P5; i += 32)
        acc += g_cum[i] * W[(size_t)i * K + w];
#pragma unroll
    for (int o = 16; o > 0; o >>= 1)
        acc += __shfl_down_sync(0xffffffffu, acc, o);
    if (lane == 0) out[w] = acc;
}

// ---------------------------------------------------------------------------
extern "C" void kernel_launch(void* const* d_in, const int* in_sizes, int n_in,
                              void* d_out, int out_size) {
    const float* X  = (const float*)d_in[0];
    const float* mu = (const float*)d_in[1];
    const float* W  = (const float*)d_in[2];
    float* out = (float*)d_out;

    const int P5 = in_sizes[1];          // P * 5
    const int P  = P5 / NM;              // 1024
    const int N  = in_sizes[0] / P;      // 100000
    const int K  = in_sizes[2] / P5;     // 8

    const int G = 592;                    // 4 blocks/SM, single wave

    k_moments<<<G, P / 4>>>(X, N, P, G);
    dim3 gridA(P / 32, NSLC);
    k_reduceA<<<gridA, 256>>>(P, G);

    if (K == 8 && P <= 1024) {
        k_finish8<<<1, 1024>>>(mu, W, out, N, P);
    } else {
        k_reduceB<<<(P + 127) / 128, 128>>>(mu, N, P);
        k_project_gen<<<K, 32>>>(W, out, P5, K);
    }
}

// round 8
// speedup vs baseline: 1.0749x; 1.0749x over previous
#include <cuda_runtime.h>

// ---------------------------------------------------------------------------
// CumulantSOAP: single-pass raw moments S1..S5 per column of X (N x P),
// 2-stage fp32 partial reduction; final kernel fuses slice-fold + fp32
// cumulant algebra + mu subtraction + projection (cum - mu) @ W.
// ---------------------------------------------------------------------------

#define NM    5
#define GMAX  740
#define PMAX  1024
#define NSLC  8          // stage-A slice count

// Scratch (no cudaMalloc allowed)
__device__ float g_partial[NM * GMAX * PMAX];    // [m][block][col]
__device__ float g_partial2[NM * NSLC * PMAX];   // [m][slice][col]
__device__ float g_cum[NM * PMAX];               // generic-fallback only

// ---- packed f32x2 helpers (Blackwell FFMA2 path, PTX-only) ----------------
static __device__ __forceinline__ unsigned long long f2_mul(unsigned long long a,
                                                            unsigned long long b) {
    unsigned long long d;
    asm("mul.rn.f32x2 %0, %1, %2;" : "=l"(d) : "l"(a), "l"(b));
    return d;
}
static __device__ __forceinline__ unsigned long long f2_add(unsigned long long a,
                                                            unsigned long long b) {
    unsigned long long d;
    asm("add.rn.f32x2 %0, %1, %2;" : "=l"(d) : "l"(a), "l"(b));
    return d;
}
static __device__ __forceinline__ unsigned long long f2_fma(unsigned long long a,
                                                            unsigned long long b,
                                                            unsigned long long c) {
    unsigned long long d;
    asm("fma.rn.f32x2 %0, %1, %2, %3;" : "=l"(d) : "l"(a), "l"(b), "l"(c));
    return d;
}
static __device__ __forceinline__ float2 f2_unpack(unsigned long long v) {
    float2 f;
    asm("mov.b64 {%0, %1}, %2;" : "=f"(f.x), "=f"(f.y) : "l"(v));
    return f;
}

// Accumulate one packed pair (2 elements) into 5 packed moment accumulators.
#define ACC(u, s1, s2, s3, s4, s5)                         \
    do {                                                   \
        unsigned long long _x2 = f2_mul((u), (u));         \
        unsigned long long _x3 = f2_mul(_x2, (u));         \
        (s1) = f2_add((s1), (u));                          \
        (s2) = f2_fma((u), (u), (s2));                     \
        (s3) = f2_fma(_x2, (u), (s3));                     \
        (s4) = f2_fma(_x2, _x2, (s4));                     \
        (s5) = f2_fma(_x3, _x2, (s5));                     \
    } while (0)

// ---------------------------------------------------------------------------
// Kernel 1: streaming raw moments. Block b handles rows b, b+G, b+2G, ...
// Thread t handles 4 consecutive columns (one LDG.128 per row), streaming
// (evict-first) loads since X is touched exactly once. 5 blocks/SM.
// ---------------------------------------------------------------------------
__global__ __launch_bounds__(256, 5)
void k_moments(const float* __restrict__ X, int N, int P, int G) {
    const int b = blockIdx.x;
    const int tid = threadIdx.x;
    const int col4 = tid * 4;

    unsigned long long s1a = 0ULL, s2a = 0ULL, s3a = 0ULL, s4a = 0ULL, s5a = 0ULL;
    unsigned long long s1b = 0ULL, s2b = 0ULL, s3b = 0ULL, s4b = 0ULL, s5b = 0ULL;

    const char* base = (const char*)(X + col4);
    const size_t rowBytes = (size_t)P * sizeof(float);

    int r = b;
    const int G4 = 4 * G;
    for (; r + 3 * G < N; r += G4) {
        ulonglong2 v0 = __ldcs((const ulonglong2*)(base + (size_t)r * rowBytes));
        ulonglong2 v1 = __ldcs((const ulonglong2*)(base + (size_t)(r + G) * rowBytes));
        ulonglong2 v2 = __ldcs((const ulonglong2*)(base + (size_t)(r + 2 * G) * rowBytes));
        ulonglong2 v3 = __ldcs((const ulonglong2*)(base + (size_t)(r + 3 * G) * rowBytes));
        ACC(v0.x, s1a, s2a, s3a, s4a, s5a);
        ACC(v0.y, s1b, s2b, s3b, s4b, s5b);
        ACC(v1.x, s1a, s2a, s3a, s4a, s5a);
        ACC(v1.y, s1b, s2b, s3b, s4b, s5b);
        ACC(v2.x, s1a, s2a, s3a, s4a, s5a);
        ACC(v2.y, s1b, s2b, s3b, s4b, s5b);
        ACC(v3.x, s1a, s2a, s3a, s4a, s5a);
        ACC(v3.y, s1b, s2b, s3b, s4b, s5b);
    }
    for (; r < N; r += G) {
        ulonglong2 v = __ldcs((const ulonglong2*)(base + (size_t)r * rowBytes));
        ACC(v.x, s1a, s2a, s3a, s4a, s5a);
        ACC(v.y, s1b, s2b, s3b, s4b, s5b);
    }

    const size_t GP = (size_t)G * P;
    float* out = g_partial + (size_t)b * P + col4;
    float2 a, bb;
    a = f2_unpack(s1a); bb = f2_unpack(s1b);
    *(float4*)(out + 0 * GP) = make_float4(a.x, a.y, bb.x, bb.y);
    a = f2_unpack(s2a); bb = f2_unpack(s2b);
    *(float4*)(out + 1 * GP) = make_float4(a.x, a.y, bb.x, bb.y);
    a = f2_unpack(s3a); bb = f2_unpack(s3b);
    *(float4*)(out + 2 * GP) = make_float4(a.x, a.y, bb.x, bb.y);
    a = f2_unpack(s4a); bb = f2_unpack(s4b);
    *(float4*)(out + 3 * GP) = make_float4(a.x, a.y, bb.x, bb.y);
    a = f2_unpack(s5a); bb = f2_unpack(s5b);
    *(float4*)(out + 4 * GP) = make_float4(a.x, a.y, bb.x, bb.y);
}

// ---------------------------------------------------------------------------
// Kernel 2a: stage-A reduction. grid = (P/32, NSLC). Block = 256 threads
// (32 cols x 8 subslices). All loads L2-hit (partials just written).
// ---------------------------------------------------------------------------
__global__ __launch_bounds__(256)
void k_reduceA(int P, int G) {
    const int cl = threadIdx.x & 31;
    const int ss = threadIdx.x >> 5;                 // 0..7
    const int col = blockIdx.x * 32 + cl;
    const int gs = blockIdx.y;                       // 0..NSLC-1
    const int chunk = G / NSLC;
    const int b0 = gs * chunk;
    const int b1 = (gs == NSLC - 1) ? G : b0 + chunk;
    const size_t GP = (size_t)G * P;

    float acc[NM] = {0.f, 0.f, 0.f, 0.f, 0.f};
    for (int b = b0 + ss; b < b1; b += 8) {
        const size_t off = (size_t)b * P + col;
#pragma unroll
        for (int m = 0; m < NM; m++)
            acc[m] += g_partial[(size_t)m * GP + off];
    }

    __shared__ float smem[NM][8][32];
#pragma unroll
    for (int m = 0; m < NM; m++) smem[m][ss][cl] = acc[m];
    __syncthreads();

    if (ss == 0) {
#pragma unroll
        for (int m = 0; m < NM; m++) {
            float v = 0.f;
#pragma unroll
            for (int j = 0; j < 8; j++) v += smem[m][j][cl];
            g_partial2[(size_t)m * (NSLC * PMAX) + (size_t)gs * PMAX + col] = v;
        }
    }
}

// ---------------------------------------------------------------------------
// Kernel 3 (fused finish, K == 8): one 1024-thread block; thread = column.
// ALL-fp32 (no fp64 pipe serialization). W prefetched with 10 independent
// float4 loads per thread, overlapped with the L2-hot slice fold; then a
// block reduction of 8 projection partials.
// ---------------------------------------------------------------------------
__global__ __launch_bounds__(1024)
void k_finish8(const float* __restrict__ mu, const float* __restrict__ W,
               float* __restrict__ out, int N, int P) {
    const int tid = threadIdx.x;
    const int col = tid;
    const bool active = (col < P);

    // --- prefetch W rows for this column: 40 contiguous floats (16B-aligned) ---
    float4 w[10];
    if (active) {
        const float4* wp = (const float4*)(W + (size_t)col * NM * 8);
#pragma unroll
        for (int i = 0; i < 10; i++) w[i] = __ldg(&wp[i]);
    }

    float a0 = 0.f, a1 = 0.f, a2 = 0.f, a3 = 0.f;
    float a4 = 0.f, a5 = 0.f, a6 = 0.f, a7 = 0.f;

    if (active) {
        // --- prefetch mu as scalars (col*5 stride is NOT 16B-aligned) ---
        const float* mup = mu + (size_t)col * NM;
        float muv[NM];
#pragma unroll
        for (int q = 0; q < NM; q++) muv[q] = __ldg(&mup[q]);

        // --- fold the 8 slice partials (L2-hot), fp32 ---
        float t[NM];
#pragma unroll
        for (int m = 0; m < NM; m++) {
            float v = 0.f;
#pragma unroll
            for (int j = 0; j < NSLC; j++)
                v += g_partial2[(size_t)m * (NSLC * PMAX) + (size_t)j * PMAX + col];
            t[m] = v;
        }

        // --- cumulants, fp32 algebra ---
        const float invN = 1.0f / (float)N;
        const float m1 = t[0] * invN;
        const float r2 = t[1] * invN;
        const float r3 = t[2] * invN;
        const float r4 = t[3] * invN;
        const float r5 = t[4] * invN;
        const float m2 = m1 * m1;
        const float m3 = m2 * m1;

        const float mu2 = r2 - m2;
        const float mu3 = r3 - 3.0f * m1 * r2 + 2.0f * m3;
        const float mu5 = r5 - 5.0f * m1 * r4 + 10.0f * m2 * r3 - 10.0f * m3 * r2
                          + 4.0f * m3 * m2;

        float c[NM];
        c[0] = m1                        - muv[0];
        c[1] = 0.f                       - muv[1];   // mean(centered) == 0
        c[2] = mu2                       - muv[2];
        c[3] = (mu3 - 3.0f * mu2 * mu2)  - muv[3];
        c[4] = (mu5 - 10.0f * mu2 * mu3) - muv[4];

        // --- projection partials for this column ---
#pragma unroll
        for (int q = 0; q < NM; q++) {
            const float cc = c[q];
            const float4 w0 = w[q * 2];
            const float4 w1 = w[q * 2 + 1];
            a0 += cc * w0.x; a1 += cc * w0.y; a2 += cc * w0.z; a3 += cc * w0.w;
            a4 += cc * w1.x; a5 += cc * w1.y; a6 += cc * w1.z; a7 += cc * w1.w;
        }
    }

    // --- block reduction of 8 accumulators ---
#pragma unroll
    for (int o = 16; o > 0; o >>= 1) {
        a0 += __shfl_down_sync(0xffffffffu, a0, o);
        a1 += __shfl_down_sync(0xffffffffu, a1, o);
        a2 += __shfl_down_sync(0xffffffffu, a2, o);
        a3 += __shfl_down_sync(0xffffffffu, a3, o);
        a4 += __shfl_down_sync(0xffffffffu, a4, o);
        a5 += __shfl_down_sync(0xffffffffu, a5, o);
        a6 += __shfl_down_sync(0xffffffffu, a6, o);
        a7 += __shfl_down_sync(0xffffffffu, a7, o);
    }

    __shared__ float sred[32][8];
    const int wrp = tid >> 5;
    if ((tid & 31) == 0) {
        sred[wrp][0] = a0; sred[wrp][1] = a1; sred[wrp][2] = a2; sred[wrp][3] = a3;
        sred[wrp][4] = a4; sred[wrp][5] = a5; sred[wrp][6] = a6; sred[wrp][7] = a7;
    }
    __syncthreads();
    if (tid < 8) {
        float v = 0.f;
#pragma unroll
        for (int j = 0; j < 32; j++) v += sred[j][tid];
        out[tid] = v;
    }
}

// ---------------------------------------------------------------------------
// Generic fallback path (K != 8 or P > 1024), fp32
// ---------------------------------------------------------------------------
__global__ __launch_bounds__(128)
void k_reduceB(const float* __restrict__ mu, int N, int P) {
    const int col = blockIdx.x * 128 + threadIdx.x;
    if (col >= P) return;

    float t[NM];
#pragma unroll
    for (int m = 0; m < NM; m++) {
        float v = 0.f;
#pragma unroll
        for (int j = 0; j < NSLC; j++)
            v += g_partial2[(size_t)m * (NSLC * PMAX) + (size_t)j * PMAX + col];
        t[m] = v;
    }

    const float invN = 1.0f / (float)N;
    const float m1 = t[0] * invN;
    const float r2 = t[1] * invN;
    const float r3 = t[2] * invN;
    const float r4 = t[3] * invN;
    const float r5 = t[4] * invN;
    const float m2 = m1 * m1;
    const float m3 = m2 * m1;

    const float mu2 = r2 - m2;
    const float mu3 = r3 - 3.0f * m1 * r2 + 2.0f * m3;
    const float mu5 = r5 - 5.0f * m1 * r4 + 10.0f * m2 * r3 - 10.0f * m3 * r2
                      + 4.0f * m3 * m2;

    const int j = col * NM;
    g_cum[j + 0] = m1 - mu[j + 0];
    g_cum[j + 1] = 0.f - mu[j + 1];
    g_cum[j + 2] = mu2 - mu[j + 2];
    g_cum[j + 3] = (mu3 - 3.0f * mu2 * mu2) - mu[j + 3];
    g_cum[j + 4] = (mu5 - 10.0f * mu2 * mu3) - mu[j + 4];
}

__global__ void k_project_gen(const float* __restrict__ W, float* __restrict__ out,
                              int P5, int K) {
    const int w = blockIdx.x;
    const int lane = threadIdx.x;
    float acc = 0.f;
    for (int i = lane; i < P5; i += 32)
        acc += g_cum[i] * W[(size_t)i * K + w];
#pragma unroll
    for (int o = 16; o > 0; o >>= 1)
        acc += __shfl_down_sync(0xffffffffu, acc, o);
    if (lane == 0) out[w] = acc;
}

// ---------------------------------------------------------------------------
extern "C" void kernel_launch(void* const* d_in, const int* in_sizes, int n_in,
                              void* d_out, int out_size) {
    const float* X  = (const float*)d_in[0];
    const float* mu = (const float*)d_in[1];
    const float* W  = (const float*)d_in[2];
    float* out = (float*)d_out;

    const int P5 = in_sizes[1];          // P * 5
    const int P  = P5 / NM;              // 1024
    const int N  = in_sizes[0] / P;      // 100000
    const int K  = in_sizes[2] / P5;     // 8

    const int G = 740;                    // 5 blocks/SM, single wave

    k_moments<<<G, P / 4>>>(X, N, P, G);
    dim3 gridA(P / 32, NSLC);
    k_reduceA<<<gridA, 256>>>(P, G);

    if (K == 8 && P <= 1024) {
        k_finish8<<<1, 1024>>>(mu, W, out, N, P);
    } else {
        k_reduceB<<<(P + 127) / 128, 128>>>(mu, N, P);
        k_project_gen<<<K, 32>>>(W, out, P5, K);
    }
}

// round 9
// speedup vs baseline: 1.0837x; 1.0082x over previous
#include <cuda_runtime.h>

// ---------------------------------------------------------------------------
// CumulantSOAP, fully fused single kernel:
//   phase 1 (all 740 blocks): streaming raw moments S1..S5 -> g_partial
//   phase 2 (blocks 0..255):  spin until all partials written, reduce ->
//                             g_partial2 [m][slice][col]
//   phase 3 (last reducer):   slice-fold + fp32 cumulants + (c - mu) @ W,
//                             write 8 outputs, reset counters.
// Deadlock-free: G = 740 = 148 SMs x 5 blocks -> ALL blocks co-resident.
// Deterministic: fixed summation order regardless of which block executes.
// ---------------------------------------------------------------------------

#define NM    5
#define GMAX  740
#define PMAX  1024
#define NSLC  8          // reducer slice count (256 reducer blocks = 32 colgrp x 8)

__device__ float g_partial[NM * GMAX * PMAX];    // [m][block][col]
__device__ float g_partial2[NM * NSLC * PMAX];   // [m][slice][col]
__device__ float g_cum[NM * PMAX];               // generic-fallback only
__device__ unsigned g_cnt1 = 0;
__device__ unsigned g_cnt2 = 0;

// ---- packed f32x2 helpers (Blackwell FFMA2 path, PTX-only) ----------------
static __device__ __forceinline__ unsigned long long f2_mul(unsigned long long a,
                                                            unsigned long long b) {
    unsigned long long d;
    asm("mul.rn.f32x2 %0, %1, %2;" : "=l"(d) : "l"(a), "l"(b));
    return d;
}
static __device__ __forceinline__ unsigned long long f2_add(unsigned long long a,
                                                            unsigned long long b) {
    unsigned long long d;
    asm("add.rn.f32x2 %0, %1, %2;" : "=l"(d) : "l"(a), "l"(b));
    return d;
}
static __device__ __forceinline__ unsigned long long f2_fma(unsigned long long a,
                                                            unsigned long long b,
                                                            unsigned long long c) {
    unsigned long long d;
    asm("fma.rn.f32x2 %0, %1, %2, %3;" : "=l"(d) : "l"(a), "l"(b), "l"(c));
    return d;
}
static __device__ __forceinline__ float2 f2_unpack(unsigned long long v) {
    float2 f;
    asm("mov.b64 {%0, %1}, %2;" : "=f"(f.x), "=f"(f.y) : "l"(v));
    return f;
}

#define ACC(u, s1, s2, s3, s4, s5)                         \
    do {                                                   \
        unsigned long long _x2 = f2_mul((u), (u));         \
        unsigned long long _x3 = f2_mul(_x2, (u));         \
        (s1) = f2_add((s1), (u));                          \
        (s2) = f2_fma((u), (u), (s2));                     \
        (s3) = f2_fma(_x2, (u), (s3));                     \
        (s4) = f2_fma(_x2, _x2, (s4));                     \
        (s5) = f2_fma(_x3, _x2, (s5));                     \
    } while (0)

// ---------------------------------------------------------------------------
__global__ __launch_bounds__(256, 5)
void k_fused(const float* __restrict__ X, const float* __restrict__ mu,
             const float* __restrict__ W, float* __restrict__ out,
             int N, int P, int G) {
    const int b = blockIdx.x;
    const int tid = threadIdx.x;

    // ================= phase 1: streaming raw moments =================
    {
        const int col4 = tid * 4;
        unsigned long long s1a = 0ULL, s2a = 0ULL, s3a = 0ULL, s4a = 0ULL, s5a = 0ULL;
        unsigned long long s1b = 0ULL, s2b = 0ULL, s3b = 0ULL, s4b = 0ULL, s5b = 0ULL;

        const char* base = (const char*)(X + col4);
        const size_t rowBytes = (size_t)P * sizeof(float);

        int r = b;
        const int G4 = 4 * G;
        for (; r + 3 * G < N; r += G4) {
            ulonglong2 v0 = __ldcs((const ulonglong2*)(base + (size_t)r * rowBytes));
            ulonglong2 v1 = __ldcs((const ulonglong2*)(base + (size_t)(r + G) * rowBytes));
            ulonglong2 v2 = __ldcs((const ulonglong2*)(base + (size_t)(r + 2 * G) * rowBytes));
            ulonglong2 v3 = __ldcs((const ulonglong2*)(base + (size_t)(r + 3 * G) * rowBytes));
            ACC(v0.x, s1a, s2a, s3a, s4a, s5a);
            ACC(v0.y, s1b, s2b, s3b, s4b, s5b);
            ACC(v1.x, s1a, s2a, s3a, s4a, s5a);
            ACC(v1.y, s1b, s2b, s3b, s4b, s5b);
            ACC(v2.x, s1a, s2a, s3a, s4a, s5a);
            ACC(v2.y, s1b, s2b, s3b, s4b, s5b);
            ACC(v3.x, s1a, s2a, s3a, s4a, s5a);
            ACC(v3.y, s1b, s2b, s3b, s4b, s5b);
        }
        for (; r < N; r += G) {
            ulonglong2 v = __ldcs((const ulonglong2*)(base + (size_t)r * rowBytes));
            ACC(v.x, s1a, s2a, s3a, s4a, s5a);
            ACC(v.y, s1b, s2b, s3b, s4b, s5b);
        }

        const size_t GP = (size_t)G * P;
        float* o = g_partial + (size_t)b * P + col4;
        float2 a, bb;
        a = f2_unpack(s1a); bb = f2_unpack(s1b);
        *(float4*)(o + 0 * GP) = make_float4(a.x, a.y, bb.x, bb.y);
        a = f2_unpack(s2a); bb = f2_unpack(s2b);
        *(float4*)(o + 1 * GP) = make_float4(a.x, a.y, bb.x, bb.y);
        a = f2_unpack(s3a); bb = f2_unpack(s3b);
        *(float4*)(o + 2 * GP) = make_float4(a.x, a.y, bb.x, bb.y);
        a = f2_unpack(s4a); bb = f2_unpack(s4b);
        *(float4*)(o + 3 * GP) = make_float4(a.x, a.y, bb.x, bb.y);
        a = f2_unpack(s5a); bb = f2_unpack(s5b);
        *(float4*)(o + 4 * GP) = make_float4(a.x, a.y, bb.x, bb.y);
    }

    // ================= arrival =================
    __threadfence();
    __syncthreads();
    if (tid == 0) atomicAdd(&g_cnt1, 1u);

    if (b >= 32 * NSLC) return;           // only 256 reducer blocks continue

    // ================= phase 2: spin, then reduceA slot =================
    if (tid == 0) {
        while (*(volatile unsigned*)&g_cnt1 < (unsigned)G) __nanosleep(128);
    }
    __syncthreads();
    __threadfence();                       // order partial reads after spin

    {
        const int cl = tid & 31;
        const int ss = tid >> 5;                         // 0..7
        const int colgrp = b & 31;
        const int gs = b >> 5;                           // 0..NSLC-1
        const int col = colgrp * 32 + cl;
        const int chunk = G / NSLC;
        const int b0 = gs * chunk;
        const int b1 = (gs == NSLC - 1) ? G : b0 + chunk;
        const size_t GP = (size_t)G * P;

        float acc[NM] = {0.f, 0.f, 0.f, 0.f, 0.f};
        for (int bb = b0 + ss; bb < b1; bb += 8) {
            const size_t off = (size_t)bb * P + col;
#pragma unroll
            for (int m = 0; m < NM; m++)
                acc[m] += g_partial[(size_t)m * GP + off];
        }

        __shared__ float smem[NM][8][32];
#pragma unroll
        for (int m = 0; m < NM; m++) smem[m][ss][cl] = acc[m];
        __syncthreads();

        if (ss == 0) {
#pragma unroll
            for (int m = 0; m < NM; m++) {
                float v = 0.f;
#pragma unroll
                for (int j = 0; j < 8; j++) v += smem[m][j][cl];
                g_partial2[(size_t)m * (NSLC * PMAX) + (size_t)gs * PMAX + col] = v;
            }
        }
    }

    __threadfence();
    __syncthreads();

    __shared__ unsigned s_ticket;
    if (tid == 0) s_ticket = atomicAdd(&g_cnt2, 1u);
    __syncthreads();
    if (s_ticket != 32 * NSLC - 1) return; // only the LAST reducer finishes

    // ================= phase 3: finish (256 threads, 4 cols each) =========
    __threadfence();                       // order partial2 reads

    float a0 = 0.f, a1 = 0.f, a2 = 0.f, a3 = 0.f;
    float a4 = 0.f, a5 = 0.f, a6 = 0.f, a7 = 0.f;
    const float invN = 1.0f / (float)N;

#pragma unroll 1
    for (int ci = 0; ci < 4; ci++) {
        const int col = tid + ci * 256;
        if (col >= P) break;

        // slice-fold (L2-hot)
        float t[NM];
#pragma unroll
        for (int m = 0; m < NM; m++) {
            float v = 0.f;
#pragma unroll
            for (int j = 0; j < NSLC; j++)
                v += g_partial2[(size_t)m * (NSLC * PMAX) + (size_t)j * PMAX + col];
            t[m] = v;
        }

        const float m1 = t[0] * invN;
        const float r2 = t[1] * invN;
        const float r3 = t[2] * invN;
        const float r4 = t[3] * invN;
        const float r5 = t[4] * invN;
        const float m2 = m1 * m1;
        const float m3 = m2 * m1;

        const float mu2 = r2 - m2;
        const float mu3 = r3 - 3.0f * m1 * r2 + 2.0f * m3;
        const float mu5 = r5 - 5.0f * m1 * r4 + 10.0f * m2 * r3 - 10.0f * m3 * r2
                          + 4.0f * m3 * m2;

        const float* mup = mu + (size_t)col * NM;   // not 16B-aligned: scalars
        float c[NM];
        c[0] = m1                        - __ldg(&mup[0]);
        c[1] = 0.f                       - __ldg(&mup[1]);
        c[2] = mu2                       - __ldg(&mup[2]);
        c[3] = (mu3 - 3.0f * mu2 * mu2)  - __ldg(&mup[3]);
        c[4] = (mu5 - 10.0f * mu2 * mu3) - __ldg(&mup[4]);

        const float4* wp = (const float4*)(W + (size_t)col * NM * 8);
#pragma unroll
        for (int q = 0; q < NM; q++) {
            const float cc = c[q];
            const float4 w0 = __ldg(&wp[q * 2]);
            const float4 w1 = __ldg(&wp[q * 2 + 1]);
            a0 += cc * w0.x; a1 += cc * w0.y; a2 += cc * w0.z; a3 += cc * w0.w;
            a4 += cc * w1.x; a5 += cc * w1.y; a6 += cc * w1.z; a7 += cc * w1.w;
        }
    }

    // block reduction of 8 accumulators (8 warps)
#pragma unroll
    for (int o = 16; o > 0; o >>= 1) {
        a0 += __shfl_down_sync(0xffffffffu, a0, o);
        a1 += __shfl_down_sync(0xffffffffu, a1, o);
        a2 += __shfl_down_sync(0xffffffffu, a2, o);
        a3 += __shfl_down_sync(0xffffffffu, a3, o);
        a4 += __shfl_down_sync(0xffffffffu, a4, o);
        a5 += __shfl_down_sync(0xffffffffu, a5, o);
        a6 += __shfl_down_sync(0xffffffffu, a6, o);
        a7 += __shfl_down_sync(0xffffffffu, a7, o);
    }

    __shared__ float sred[8][8];
    const int wrp = tid >> 5;
    if ((tid & 31) == 0) {
        sred[wrp][0] = a0; sred[wrp][1] = a1; sred[wrp][2] = a2; sred[wrp][3] = a3;
        sred[wrp][4] = a4; sred[wrp][5] = a5; sred[wrp][6] = a6; sred[wrp][7] = a7;
    }
    __syncthreads();
    if (tid < 8) {
        float v = 0.f;
#pragma unroll
        for (int j = 0; j < 8; j++) v += sred[j][tid];
        out[tid] = v;
    }

    // reset counters for the next graph replay (all spins are long past)
    if (tid == 0) {
        g_cnt1 = 0;
        g_cnt2 = 0;
        __threadfence();
    }
}

// ---------------------------------------------------------------------------
// Generic fallback path (K != 8 or P != 1024): 3 separate kernels, fp32.
// ---------------------------------------------------------------------------
__global__ __launch_bounds__(256, 5)
void k_moments(const float* __restrict__ X, int N, int P, int G) {
    const int b = blockIdx.x;
    const int tid = threadIdx.x;
    const int col4 = tid * 4;

    unsigned long long s1a = 0ULL, s2a = 0ULL, s3a = 0ULL, s4a = 0ULL, s5a = 0ULL;
    unsigned long long s1b = 0ULL, s2b = 0ULL, s3b = 0ULL, s4b = 0ULL, s5b = 0ULL;

    const char* base = (const char*)(X + col4);
    const size_t rowBytes = (size_t)P * sizeof(float);

    for (int r = b; r < N; r += G) {
        ulonglong2 v = __ldcs((const ulonglong2*)(base + (size_t)r * rowBytes));
        ACC(v.x, s1a, s2a, s3a, s4a, s5a);
        ACC(v.y, s1b, s2b, s3b, s4b, s5b);
    }

    const size_t GP = (size_t)G * P;
    float* o = g_partial + (size_t)b * P + col4;
    float2 a, bb;
    a = f2_unpack(s1a); bb = f2_unpack(s1b);
    *(float4*)(o + 0 * GP) = make_float4(a.x, a.y, bb.x, bb.y);
    a = f2_unpack(s2a); bb = f2_unpack(s2b);
    *(float4*)(o + 1 * GP) = make_float4(a.x, a.y, bb.x, bb.y);
    a = f2_unpack(s3a); bb = f2_unpack(s3b);
    *(float4*)(o + 2 * GP) = make_float4(a.x, a.y, bb.x, bb.y);
    a = f2_unpack(s4a); bb = f2_unpack(s4b);
    *(float4*)(o + 3 * GP) = make_float4(a.x, a.y, bb.x, bb.y);
    a = f2_unpack(s5a); bb = f2_unpack(s5b);
    *(float4*)(o + 4 * GP) = make_float4(a.x, a.y, bb.x, bb.y);
}

__global__ __launch_bounds__(128)
void k_reduceB_gen(const float* __restrict__ mu, int N, int P, int G) {
    const int col = blockIdx.x * 128 + threadIdx.x;
    if (col >= P) return;
    const size_t GP = (size_t)G * P;

    float t[NM] = {0.f, 0.f, 0.f, 0.f, 0.f};
    for (int bb = 0; bb < G; bb++) {
#pragma unroll
        for (int m = 0; m < NM; m++)
            t[m] += g_partial[(size_t)m * GP + (size_t)bb * P + col];
    }

    const float invN = 1.0f / (float)N;
    const float m1 = t[0] * invN;
    const float r2 = t[1] * invN;
    const float r3 = t[2] * invN;
    const float r4 = t[3] * invN;
    const float r5 = t[4] * invN;
    const float m2 = m1 * m1;
    const float m3 = m2 * m1;

    const float mu2 = r2 - m2;
    const float mu3 = r3 - 3.0f * m1 * r2 + 2.0f * m3;
    const float mu5 = r5 - 5.0f * m1 * r4 + 10.0f * m2 * r3 - 10.0f * m3 * r2
                      + 4.0f * m3 * m2;

    const int j = col * NM;
    g_cum[j + 0] = m1 - mu[j + 0];
    g_cum[j + 1] = 0.f - mu[j + 1];
    g_cum[j + 2] = mu2 - mu[j + 2];
    g_cum[j + 3] = (mu3 - 3.0f * mu2 * mu2) - mu[j + 3];
    g_cum[j + 4] = (mu5 - 10.0f * mu2 * mu3) - mu[j + 4];
}

__global__ void k_project_gen(const float* __restrict__ W, float* __restrict__ out,
                              int P5, int K) {
    const int w = blockIdx.x;
    const int lane = threadIdx.x;
    float acc = 0.f;
    for (int i = lane; i < P5; i += 32)
        acc += g_cum[i] * W[(size_t)i * K + w];
#pragma unroll
    for (int o = 16; o > 0; o >>= 1)
        acc += __shfl_down_sync(0xffffffffu, acc, o);
    if (lane == 0) out[w] = acc;
}

// ---------------------------------------------------------------------------
extern "C" void kernel_launch(void* const* d_in, const int* in_sizes, int n_in,
                              void* d_out, int out_size) {
    const float* X  = (const float*)d_in[0];
    const float* mu = (const float*)d_in[1];
    const float* W  = (const float*)d_in[2];
    float* out = (float*)d_out;

    const int P5 = in_sizes[1];          // P * 5
    const int P  = P5 / NM;              // 1024
    const int N  = in_sizes[0] / P;      // 100000
    const int K  = in_sizes[2] / P5;     // 8

    const int G = 740;                    // 148 SMs x 5 blocks: ONE resident wave

    if (K == 8 && P == 1024) {
        k_fused<<<G, P / 4>>>(X, mu, W, out, N, P, G);
    } else {
        const int Gg = 592;
        k_moments<<<Gg, P / 4>>>(X, N, P, Gg);
        k_reduceB_gen<<<(P + 127) / 128, 128>>>(mu, N, P, Gg);
        k_project_gen<<<K, 32>>>(W, out, P5, K);
    }
}

// round 10
// speedup vs baseline: 1.1028x; 1.0175x over previous
#include <cuda_runtime.h>

// ---------------------------------------------------------------------------
// CumulantSOAP, fully fused single kernel with PER-SLICE arrival counters:
//   phase 1 (all 740 blocks): streaming raw moments S1..S5 -> g_partial;
//                             arrive on g_cslice[b/CHUNK].
//   phase 2 (blocks 0..255):  reducer (colgrp, gs) spins ONLY on its slice's
//                             counter -> overlaps phase-1 stragglers; reduces
//                             93 partials -> g_partial2[m][gs][col].
//   phase 3 (last reducer):   slice-fold + fp32 cumulants + (c - mu) @ W,
//                             write 8 outputs, reset counters.
// Deadlock-free: G = 740 = 148 SMs x 5 blocks -> ALL blocks co-resident.
// Deterministic: fixed partial assignment + fixed summation order.
// ---------------------------------------------------------------------------

#define NM    5
#define GMAX  740
#define PMAX  1024
#define NSLC  8          // slices; 256 reducer blocks = 32 colgrp x 8 slices
#define CHUNK 93         // ceil(740/8); last slice has 740-93*7 = 89 blocks

__device__ float g_partial[NM * GMAX * PMAX];    // [m][block][col]
__device__ float g_partial2[NM * NSLC * PMAX];   // [m][slice][col]
__device__ float g_cum[NM * PMAX];               // generic-fallback only
__device__ unsigned g_cslice[NSLC];              // per-slice arrival counters
__device__ unsigned g_cnt2 = 0;                  // reducer completion tickets

// ---- packed f32x2 helpers (Blackwell FFMA2 path, PTX-only) ----------------
static __device__ __forceinline__ unsigned long long f2_mul(unsigned long long a,
                                                            unsigned long long b) {
    unsigned long long d;
    asm("mul.rn.f32x2 %0, %1, %2;" : "=l"(d) : "l"(a), "l"(b));
    return d;
}
static __device__ __forceinline__ unsigned long long f2_add(unsigned long long a,
                                                            unsigned long long b) {
    unsigned long long d;
    asm("add.rn.f32x2 %0, %1, %2;" : "=l"(d) : "l"(a), "l"(b));
    return d;
}
static __device__ __forceinline__ unsigned long long f2_fma(unsigned long long a,
                                                            unsigned long long b,
                                                            unsigned long long c) {
    unsigned long long d;
    asm("fma.rn.f32x2 %0, %1, %2, %3;" : "=l"(d) : "l"(a), "l"(b), "l"(c));
    return d;
}
static __device__ __forceinline__ float2 f2_unpack(unsigned long long v) {
    float2 f;
    asm("mov.b64 {%0, %1}, %2;" : "=f"(f.x), "=f"(f.y) : "l"(v));
    return f;
}

#define ACC(u, s1, s2, s3, s4, s5)                         \
    do {                                                   \
        unsigned long long _x2 = f2_mul((u), (u));         \
        unsigned long long _x3 = f2_mul(_x2, (u));         \
        (s1) = f2_add((s1), (u));                          \
        (s2) = f2_fma((u), (u), (s2));                     \
        (s3) = f2_fma(_x2, (u), (s3));                     \
        (s4) = f2_fma(_x2, _x2, (s4));                     \
        (s5) = f2_fma(_x3, _x2, (s5));                     \
    } while (0)

// ---------------------------------------------------------------------------
__global__ __launch_bounds__(256, 5)
void k_fused(const float* __restrict__ X, const float* __restrict__ mu,
             const float* __restrict__ W, float* __restrict__ out,
             int N, int P, int G) {
    const int b = blockIdx.x;
    const int tid = threadIdx.x;

    // ================= phase 1: streaming raw moments =================
    {
        const int col4 = tid * 4;
        unsigned long long s1a = 0ULL, s2a = 0ULL, s3a = 0ULL, s4a = 0ULL, s5a = 0ULL;
        unsigned long long s1b = 0ULL, s2b = 0ULL, s3b = 0ULL, s4b = 0ULL, s5b = 0ULL;

        const char* base = (const char*)(X + col4);
        const size_t rowBytes = (size_t)P * sizeof(float);

        int r = b;
        const int G4 = 4 * G;
        for (; r + 3 * G < N; r += G4) {
            ulonglong2 v0 = __ldcs((const ulonglong2*)(base + (size_t)r * rowBytes));
            ulonglong2 v1 = __ldcs((const ulonglong2*)(base + (size_t)(r + G) * rowBytes));
            ulonglong2 v2 = __ldcs((const ulonglong2*)(base + (size_t)(r + 2 * G) * rowBytes));
            ulonglong2 v3 = __ldcs((const ulonglong2*)(base + (size_t)(r + 3 * G) * rowBytes));
            ACC(v0.x, s1a, s2a, s3a, s4a, s5a);
            ACC(v0.y, s1b, s2b, s3b, s4b, s5b);
            ACC(v1.x, s1a, s2a, s3a, s4a, s5a);
            ACC(v1.y, s1b, s2b, s3b, s4b, s5b);
            ACC(v2.x, s1a, s2a, s3a, s4a, s5a);
            ACC(v2.y, s1b, s2b, s3b, s4b, s5b);
            ACC(v3.x, s1a, s2a, s3a, s4a, s5a);
            ACC(v3.y, s1b, s2b, s3b, s4b, s5b);
        }
        for (; r < N; r += G) {
            ulonglong2 v = __ldcs((const ulonglong2*)(base + (size_t)r * rowBytes));
            ACC(v.x, s1a, s2a, s3a, s4a, s5a);
            ACC(v.y, s1b, s2b, s3b, s4b, s5b);
        }

        const size_t GP = (size_t)G * P;
        float* o = g_partial + (size_t)b * P + col4;
        float2 a, bb;
        a = f2_unpack(s1a); bb = f2_unpack(s1b);
        *(float4*)(o + 0 * GP) = make_float4(a.x, a.y, bb.x, bb.y);
        a = f2_unpack(s2a); bb = f2_unpack(s2b);
        *(float4*)(o + 1 * GP) = make_float4(a.x, a.y, bb.x, bb.y);
        a = f2_unpack(s3a); bb = f2_unpack(s3b);
        *(float4*)(o + 2 * GP) = make_float4(a.x, a.y, bb.x, bb.y);
        a = f2_unpack(s4a); bb = f2_unpack(s4b);
        *(float4*)(o + 3 * GP) = make_float4(a.x, a.y, bb.x, bb.y);
        a = f2_unpack(s5a); bb = f2_unpack(s5b);
        *(float4*)(o + 4 * GP) = make_float4(a.x, a.y, bb.x, bb.y);
    }

    // ================= arrival (per-slice) =================
    __threadfence();
    __syncthreads();
    if (tid == 0) {
        int s = b / CHUNK;
        if (s >= NSLC) s = NSLC - 1;
        atomicAdd(&g_cslice[s], 1u);
    }

    if (b >= 32 * NSLC) return;           // only 256 reducer blocks continue

    // ================= phase 2: wait for OWN slice, then reduce ==========
    const int gs = b >> 5;                // 0..7 (slice)
    const int colgrp = b & 31;
    const int b0 = gs * CHUNK;
    const int b1 = (b0 + CHUNK < G) ? (b0 + CHUNK) : G;
    const unsigned target = (unsigned)(b1 - b0);

    if (tid == 0) {
        while (*(volatile unsigned*)&g_cslice[gs] < target) __nanosleep(128);
    }
    __syncthreads();
    __threadfence();                       // order partial reads after spin

    {
        const int cl = tid & 31;
        const int ss = tid >> 5;                         // 0..7
        const int col = colgrp * 32 + cl;
        const size_t GP = (size_t)G * P;

        float acc[NM] = {0.f, 0.f, 0.f, 0.f, 0.f};
        for (int bb = b0 + ss; bb < b1; bb += 8) {
            const size_t off = (size_t)bb * P + col;
#pragma unroll
            for (int m = 0; m < NM; m++)
                acc[m] += g_partial[(size_t)m * GP + off];
        }

        __shared__ float smem[NM][8][32];
#pragma unroll
        for (int m = 0; m < NM; m++) smem[m][ss][cl] = acc[m];
        __syncthreads();

        if (ss == 0) {
#pragma unroll
            for (int m = 0; m < NM; m++) {
                float v = 0.f;
#pragma unroll
                for (int j = 0; j < 8; j++) v += smem[m][j][cl];
                g_partial2[(size_t)m * (NSLC * PMAX) + (size_t)gs * PMAX + col] = v;
            }
        }
    }

    __threadfence();
    __syncthreads();

    __shared__ unsigned s_ticket;
    if (tid == 0) s_ticket = atomicAdd(&g_cnt2, 1u);
    __syncthreads();
    if (s_ticket != 32 * NSLC - 1) return; // only the LAST reducer finishes

    // ================= phase 3: finish (256 threads, 4 cols each) =========
    __threadfence();                       // order partial2 reads

    float a0 = 0.f, a1 = 0.f, a2 = 0.f, a3 = 0.f;
    float a4 = 0.f, a5 = 0.f, a6 = 0.f, a7 = 0.f;
    const float invN = 1.0f / (float)N;

#pragma unroll 1
    for (int ci = 0; ci < 4; ci++) {
        const int col = tid + ci * 256;
        if (col >= P) break;

        float t[NM];
#pragma unroll
        for (int m = 0; m < NM; m++) {
            float v = 0.f;
#pragma unroll
            for (int j = 0; j < NSLC; j++)
                v += g_partial2[(size_t)m * (NSLC * PMAX) + (size_t)j * PMAX + col];
            t[m] = v;
        }

        const float m1 = t[0] * invN;
        const float r2 = t[1] * invN;
        const float r3 = t[2] * invN;
        const float r4 = t[3] * invN;
        const float r5 = t[4] * invN;
        const float m2 = m1 * m1;
        const float m3 = m2 * m1;

        const float mu2 = r2 - m2;
        const float mu3 = r3 - 3.0f * m1 * r2 + 2.0f * m3;
        const float mu5 = r5 - 5.0f * m1 * r4 + 10.0f * m2 * r3 - 10.0f * m3 * r2
                          + 4.0f * m3 * m2;

        const float* mup = mu + (size_t)col * NM;   // not 16B-aligned: scalars
        float c[NM];
        c[0] = m1                        - __ldg(&mup[0]);
        c[1] = 0.f                       - __ldg(&mup[1]);
        c[2] = mu2                       - __ldg(&mup[2]);
        c[3] = (mu3 - 3.0f * mu2 * mu2)  - __ldg(&mup[3]);
        c[4] = (mu5 - 10.0f * mu2 * mu3) - __ldg(&mup[4]);

        const float4* wp = (const float4*)(W + (size_t)col * NM * 8);
#pragma unroll
        for (int q = 0; q < NM; q++) {
            const float cc = c[q];
            const float4 w0 = __ldg(&wp[q * 2]);
            const float4 w1 = __ldg(&wp[q * 2 + 1]);
            a0 += cc * w0.x; a1 += cc * w0.y; a2 += cc * w0.z; a3 += cc * w0.w;
            a4 += cc * w1.x; a5 += cc * w1.y; a6 += cc * w1.z; a7 += cc * w1.w;
        }
    }

    // block reduction of 8 accumulators (8 warps)
#pragma unroll
    for (int o = 16; o > 0; o >>= 1) {
        a0 += __shfl_down_sync(0xffffffffu, a0, o);
        a1 += __shfl_down_sync(0xffffffffu, a1, o);
        a2 += __shfl_down_sync(0xffffffffu, a2, o);
        a3 += __shfl_down_sync(0xffffffffu, a3, o);
        a4 += __shfl_down_sync(0xffffffffu, a4, o);
        a5 += __shfl_down_sync(0xffffffffu, a5, o);
        a6 += __shfl_down_sync(0xffffffffu, a6, o);
        a7 += __shfl_down_sync(0xffffffffu, a7, o);
    }

    __shared__ float sred[8][8];
    const int wrp = tid >> 5;
    if ((tid & 31) == 0) {
        sred[wrp][0] = a0; sred[wrp][1] = a1; sred[wrp][2] = a2; sred[wrp][3] = a3;
        sred[wrp][4] = a4; sred[wrp][5] = a5; sred[wrp][6] = a6; sred[wrp][7] = a7;
    }
    __syncthreads();
    if (tid < 8) {
        float v = 0.f;
#pragma unroll
        for (int j = 0; j < 8; j++) v += sred[j][tid];
        out[tid] = v;
    }

    // reset counters for the next graph replay (all spins are long past)
    if (tid == 0) {
#pragma unroll
        for (int s = 0; s < NSLC; s++) g_cslice[s] = 0;
        g_cnt2 = 0;
        __threadfence();
    }
}

// ---------------------------------------------------------------------------
// Generic fallback path (K != 8 or P != 1024): 3 separate kernels, fp32.
// ---------------------------------------------------------------------------
__global__ __launch_bounds__(256, 5)
void k_moments(const float* __restrict__ X, int N, int P, int G) {
    const int b = blockIdx.x;
    const int tid = threadIdx.x;
    const int col4 = tid * 4;

    unsigned long long s1a = 0ULL, s2a = 0ULL, s3a = 0ULL, s4a = 0ULL, s5a = 0ULL;
    unsigned long long s1b = 0ULL, s2b = 0ULL, s3b = 0ULL, s4b = 0ULL, s5b = 0ULL;

    const char* base = (const char*)(X + col4);
    const size_t rowBytes = (size_t)P * sizeof(float);

    for (int r = b; r < N; r += G) {
        ulonglong2 v = __ldcs((const ulonglong2*)(base + (size_t)r * rowBytes));
        ACC(v.x, s1a, s2a, s3a, s4a, s5a);
        ACC(v.y, s1b, s2b, s3b, s4b, s5b);
    }

    const size_t GP = (size_t)G * P;
    float* o = g_partial + (size_t)b * P + col4;
    float2 a, bb;
    a = f2_unpack(s1a); bb = f2_unpack(s1b);
    *(float4*)(o + 0 * GP) = make_float4(a.x, a.y, bb.x, bb.y);
    a = f2_unpack(s2a); bb = f2_unpack(s2b);
    *(float4*)(o + 1 * GP) = make_float4(a.x, a.y, bb.x, bb.y);
    a = f2_unpack(s3a); bb = f2_unpack(s3b);
    *(float4*)(o + 2 * GP) = make_float4(a.x, a.y, bb.x, bb.y);
    a = f2_unpack(s4a); bb = f2_unpack(s4b);
    *(float4*)(o + 3 * GP) = make_float4(a.x, a.y, bb.x, bb.y);
    a = f2_unpack(s5a); bb = f2_unpack(s5b);
    *(float4*)(o + 4 * GP) = make_float4(a.x, a.y, bb.x, bb.y);
}

__global__ __launch_bounds__(128)
void k_reduceB_gen(const float* __restrict__ mu, int N, int P, int G) {
    const int col = blockIdx.x * 128 + threadIdx.x;
    if (col >= P) return;
    const size_t GP = (size_t)G * P;

    float t[NM] = {0.f, 0.f, 0.f, 0.f, 0.f};
    for (int bb = 0; bb < G; bb++) {
#pragma unroll
        for (int m = 0; m < NM; m++)
            t[m] += g_partial[(size_t)m * GP + (size_t)bb * P + col];
    }

    const float invN = 1.0f / (float)N;
    const float m1 = t[0] * invN;
    const float r2 = t[1] * invN;
    const float r3 = t[2] * invN;
    const float r4 = t[3] * invN;
    const float r5 = t[4] * invN;
    const float m2 = m1 * m1;
    const float m3 = m2 * m1;

    const float mu2 = r2 - m2;
    const float mu3 = r3 - 3.0f * m1 * r2 + 2.0f * m3;
    const float mu5 = r5 - 5.0f * m1 * r4 + 10.0f * m2 * r3 - 10.0f * m3 * r2
                      + 4.0f * m3 * m2;

    const int j = col * NM;
    g_cum[j + 0] = m1 - mu[j + 0];
    g_cum[j + 1] = 0.f - mu[j + 1];
    g_cum[j + 2] = mu2 - mu[j + 2];
    g_cum[j + 3] = (mu3 - 3.0f * mu2 * mu2) - mu[j + 3];
    g_cum[j + 4] = (mu5 - 10.0f * mu2 * mu3) - mu[j + 4];
}

__global__ void k_project_gen(const float* __restrict__ W, float* __restrict__ out,
                              int P5, int K) {
    const int w = blockIdx.x;
    const int lane = threadIdx.x;
    float acc = 0.f;
    for (int i = lane; i < P5; i += 32)
        acc += g_cum[i] * W[(size_t)i * K + w];
#pragma unroll
    for (int o = 16; o > 0; o >>= 1)
        acc += __shfl_down_sync(0xffffffffu, acc, o);
    if (lane == 0) out[w] = acc;
}

// ---------------------------------------------------------------------------
extern "C" void kernel_launch(void* const* d_in, const int* in_sizes, int n_in,
                              void* d_out, int out_size) {
    const float* X  = (const float*)d_in[0];
    const float* mu = (const float*)d_in[1];
    const float* W  = (const float*)d_in[2];
    float* out = (float*)d_out;

    const int P5 = in_sizes[1];          // P * 5
    const int P  = P5 / NM;              // 1024
    const int N  = in_sizes[0] / P;      // 100000
    const int K  = in_sizes[2] / P5;     // 8

    const int G = 740;                    // 148 SMs x 5 blocks: ONE resident wave

    if (K == 8 && P == 1024) {
        k_fused<<<G, P / 4>>>(X, mu, W, out, N, P, G);
    } else {
        const int Gg = 592;
        k_moments<<<Gg, P / 4>>>(X, N, P, Gg);
        k_reduceB_gen<<<(P + 127) / 128, 128>>>(mu, N, P, Gg);
        k_project_gen<<<K, 32>>>(W, out, P5, K);
    }
}